// round 13
// baseline (speedup 1.0000x reference)
#include <cuda_runtime.h>
#include <math.h>

#define BB  256
#define GG  2048
#define FF  128
#define RNN 512
#define KK  128

// Scratch (no allocation allowed) ------------------------------------------
__device__ float g_scorer[BB * FF];
__device__ float g_scores[BB * GG];
__device__ float g_tvals [BB * KK];
__device__ int   g_tidx  [BB * KK];

// --------------------------------------------------------------------------
// K1: scorer[b,f] = tanh(h_t[b,:] @ W[:,f] + bias[f]) / ||tanh||
//     (round-6 version: 128 blocks x 256 threads, 2 batches/block)
// --------------------------------------------------------------------------
__global__ void k1_scorer(const float* __restrict__ h_t,
                          const float* __restrict__ W,
                          const float* __restrict__ bmap) {
    int tid = threadIdx.x;               // 256
    int bq = tid >> 7, f = tid & 127;
    int b0 = blockIdx.x * 2;
    __shared__ float Ws[64 * 128];
    __shared__ float hs[2 * RNN];
    __shared__ float red2[8];
    for (int i = tid; i < 2 * RNN; i += 256)
        hs[i] = h_t[b0 * RNN + i];
    float acc = bmap[f];
    float4* Ws4 = reinterpret_cast<float4*>(Ws);
    for (int c = 0; c < RNN / 64; ++c) {
        __syncthreads();
        const float4* W4 = reinterpret_cast<const float4*>(W + c * 64 * 128);
#pragma unroll
        for (int i = 0; i < 8; ++i) Ws4[tid + i * 256] = W4[tid + i * 256];
        __syncthreads();
        const float* hb = hs + bq * RNN + c * 64;
#pragma unroll
        for (int r = 0; r < 64; ++r) acc = fmaf(hb[r], Ws[r * 128 + f], acc);
    }
    float s = tanhf(acc);
    float q = s * s;
#pragma unroll
    for (int o = 16; o > 0; o >>= 1) q += __shfl_xor_sync(0xffffffffu, q, o);
    int warp = tid >> 5, lane = tid & 31;
    if (lane == 0) red2[warp] = q;
    __syncthreads();
    float nrm = red2[bq * 4] + red2[bq * 4 + 1] + red2[bq * 4 + 2] + red2[bq * 4 + 3];
    g_scorer[(b0 + bq) * FF + f] = s * rsqrtf(nrm);
}

// --------------------------------------------------------------------------
// K2: scores[b,g] = node_embs[b,g,:] . scorer[b,:] + mask[b,g]
//     default cache policy: the trailing ~L2-capacity of node_embs stays
//     resident so k4's gathers hit L2 instead of DRAM.
// --------------------------------------------------------------------------
__global__ void k2_scores(const float* __restrict__ ne,
                          const float* __restrict__ mask) {
    int b = blockIdx.x;
    int gbase = blockIdx.y * 64;
    __shared__ float4 sc[FF / 4];
    int tid = threadIdx.x;                   // 256
    if (tid < FF / 4)
        sc[tid] = reinterpret_cast<const float4*>(g_scorer + b * FF)[tid];
    __syncthreads();
    int warp = tid >> 5, lane = tid & 31;
    float4 s = sc[lane];
    const float4* base = reinterpret_cast<const float4*>(ne) + (size_t)b * GG * (FF / 4);
    int g0 = gbase + warp * 8;
    float d[8];
#pragma unroll
    for (int j = 0; j < 8; ++j) {
        float4 v = __ldg(base + (size_t)(g0 + j) * (FF / 4) + lane);
        d[j] = v.x * s.x + v.y * s.y + v.z * s.z + v.w * s.w;
    }
#pragma unroll
    for (int o = 16; o > 0; o >>= 1) {
#pragma unroll
        for (int j = 0; j < 8; ++j) d[j] += __shfl_xor_sync(0xffffffffu, d[j], o);
    }
    if (lane == 0) {
        const float4* mb = reinterpret_cast<const float4*>(mask + b * GG + g0);
        float4* ob = reinterpret_cast<float4*>(g_scores + b * GG + g0);
        float4 m0 = mb[0], m1 = mb[1];
        ob[0] = make_float4(d[0] + m0.x, d[1] + m0.y, d[2] + m0.z, d[3] + m0.w);
        ob[1] = make_float4(d[4] + m1.x, d[5] + m1.y, d[6] + m1.z, d[7] + m1.w);
    }
}

// --------------------------------------------------------------------------
// K3: 32-bit radix-select top-128 + rank-by-count emit + logsumexp
//     (round-6 version: plain smem atomics)
// --------------------------------------------------------------------------
__device__ __forceinline__ unsigned f2u(float f) {
    unsigned u = __float_as_uint(f);
    return (u & 0x80000000u) ? ~u : (u | 0x80000000u);
}
__device__ __forceinline__ float u2f(unsigned u) {
    unsigned b = (u & 0x80000000u) ? (u & 0x7FFFFFFFu) : ~u;
    return __uint_as_float(b);
}

__global__ void k3_topk(float* __restrict__ policy_out) {
    const unsigned FULL = 0xffffffffu;
    int b = blockIdx.x, tid = threadIdx.x;   // 512 threads, 16 warps
    int lane = tid & 31, warp = tid >> 5;
    __shared__ float rbuf[16];
    __shared__ unsigned hist[256];
    __shared__ unsigned long long top[256];
    __shared__ unsigned sel_d, sel_sub, cnt_;
    __shared__ float s_smax;

    float v[4];
    unsigned u[4];
#pragma unroll
    for (int j = 0; j < 4; ++j) {
        v[j] = g_scores[b * GG + tid + j * 512];
        u[j] = f2u(v[j]);
    }

    unsigned prefix = 0, kneed = KK;
    for (int shift = 24; shift >= 0; shift -= 8) {
        unsigned maskhi = (shift == 24) ? 0u : (0xFFFFFFFFu << (shift + 8));
        __syncthreads();
        if (tid < 256) hist[tid] = 0;
        __syncthreads();
#pragma unroll
        for (int j = 0; j < 4; ++j)
            if ((u[j] & maskhi) == prefix)
                atomicAdd(&hist[(u[j] >> shift) & 0xFFu], 1u);
        __syncthreads();
        if (tid < 32) {
            unsigned hv[8], t = 0;
#pragma unroll
            for (int q = 0; q < 8; ++q) { hv[q] = hist[tid * 8 + q]; t += hv[q]; }
            unsigned x = t;
#pragma unroll
            for (int o = 1; o < 32; o <<= 1) {
                unsigned y = __shfl_down_sync(FULL, x, o);
                if (tid + o < 32) x += y;
            }
            unsigned run = x - t;
#pragma unroll
            for (int q = 7; q >= 0; --q) { run += hv[q]; hist[tid * 8 + q] = run; }
        }
        __syncthreads();
        if (tid < 256) {
            unsigned h = hist[tid];
            unsigned hn = (tid == 255) ? 0u : hist[tid + 1];
            if (h >= kneed && hn < kneed) { sel_d = (unsigned)tid; sel_sub = hn; }
        }
        __syncthreads();
        prefix |= sel_d << shift;
        kneed -= sel_sub;
    }

    if (tid == 0) cnt_ = 0;
    __syncthreads();
#pragma unroll
    for (int j = 0; j < 4; ++j) {
        if (u[j] >= prefix) {
            unsigned p = atomicAdd(&cnt_, 1u);
            if (p < 256)
                top[p] = ((unsigned long long)u[j] << 32) |
                         (unsigned)(~(unsigned)(tid + j * 512));
        }
    }
    __syncthreads();
    unsigned n = cnt_ < 256u ? cnt_ : 256u;

    float contrib = 0.f;
    if (tid < (int)n) {
        unsigned long long key = top[tid];
        unsigned r = 0;
        for (unsigned jj = 0; jj < n; ++jj) r += (top[jj] > key);
        if (r < KK) {
            float val = u2f((unsigned)(key >> 32));
            g_tvals[b * KK + r] = tanhf(val);
            g_tidx [b * KK + r] = (int)(~(unsigned)key);
            contrib = val;
            if (r == 0) s_smax = val;
        }
    }
#pragma unroll
    for (int o = 16; o > 0; o >>= 1) contrib += __shfl_xor_sync(FULL, contrib, o);
    if (lane == 0) rbuf[warp] = contrib;
    __syncthreads();
    float sumtop = 0.f;
    if (tid == 0) {
#pragma unroll
        for (int w = 0; w < 16; ++w) sumtop += rbuf[w];
    }
    float smax = s_smax;
    __syncthreads();

    float sum = expf(v[0] - smax) + expf(v[1] - smax) +
                expf(v[2] - smax) + expf(v[3] - smax);
#pragma unroll
    for (int o = 16; o > 0; o >>= 1) sum += __shfl_xor_sync(FULL, sum, o);
    if (lane == 0) rbuf[warp] = sum;
    __syncthreads();
    if (tid == 0) {
        float x = 0.f;
#pragma unroll
        for (int w = 0; w < 16; ++w) x += rbuf[w];
        policy_out[b] = sumtop * (1.0f / KK) - (smax + logf(x));
    }
}

// --------------------------------------------------------------------------
// K4: out[b,f,k] = node_embs[b, idx[b,k], f] * tanh(val[b,k])
//     (round-6 version: 4 blocks/batch, 32-row tiles, 4 LDG.128/thread)
// --------------------------------------------------------------------------
__global__ void k4_gather(const float* __restrict__ ne, float* __restrict__ out) {
    int b = blockIdx.x, kq = blockIdx.y;     // quarter index 0..3
    int tid = threadIdx.x;                   // 256 threads
    __shared__ float tile[32 * 129];
    __shared__ float tv[32];
    __shared__ int   ti[32];
    if (tid < 32) {
        tv[tid] = g_tvals[b * KK + kq * 32 + tid];
        ti[tid] = g_tidx [b * KK + kq * 32 + tid];
    }
    __syncthreads();
    const float4* base = reinterpret_cast<const float4*>(ne) + (size_t)b * GG * (FF / 4);
    float* ob = out + (size_t)b * FF * KK + kq * 32;
#pragma unroll
    for (int it = 0; it < 4; ++it) {
        int i = tid + it * 256;              // 0..1023
        int k = i >> 5, c = i & 31;
        float4 v = base[(size_t)ti[k] * (FF / 4) + c];
        float s = tv[k];
        float* t = tile + k * 129 + c * 4;
        t[0] = v.x * s; t[1] = v.y * s; t[2] = v.z * s; t[3] = v.w * s;
    }
    __syncthreads();
#pragma unroll
    for (int it = 0; it < 4; ++it) {
        int i = tid + it * 256;              // 0..1023
        int f = i >> 3, q = i & 7;
        int k = q * 4;
        float4 w;
        w.x = tile[(k + 0) * 129 + f];
        w.y = tile[(k + 1) * 129 + f];
        w.z = tile[(k + 2) * 129 + f];
        w.w = tile[(k + 3) * 129 + f];
        *reinterpret_cast<float4*>(ob + (size_t)f * KK + k) = w;
    }
}

// --------------------------------------------------------------------------
extern "C" void kernel_launch(void* const* d_in, const int* in_sizes, int n_in,
                              void* d_out, int out_size) {
    const float* node_embs = (const float*)d_in[0];
    const float* mask      = (const float*)d_in[1];
    const float* h_t       = (const float*)d_in[2];
    const float* W_map     = (const float*)d_in[3];
    const float* b_map     = (const float*)d_in[4];
    float* out    = (float*)d_out;
    float* policy = out + (size_t)BB * FF * KK;   // outputs: [B,F,K] then [B]

    k1_scorer<<<BB / 2, 256>>>(h_t, W_map, b_map);
    k2_scores<<<dim3(BB, GG / 64), 256>>>(node_embs, mask);
    k3_topk<<<BB, 512>>>(policy);
    k4_gather<<<dim3(BB, 4), 256>>>(node_embs, out);
}

// round 14
// speedup vs baseline: 1.1340x; 1.1340x over previous
#include <cuda_runtime.h>
#include <math.h>

#define BB  256
#define GG  2048
#define FF  128
#define RNN 512
#define KK  128

// Scratch (no allocation allowed) ------------------------------------------
__device__ float g_scorer[BB * FF];
__device__ float g_scores[BB * GG];
__device__ float g_tvals [BB * KK];
__device__ int   g_tidx  [BB * KK];

// --------------------------------------------------------------------------
// K1: scorer[b,f] = tanh(h_t[b,:] @ W[:,f] + bias[f]) / ||tanh||
//     128 blocks x 256 threads, 2 batches/block, W staged via smem chunks
// --------------------------------------------------------------------------
__global__ void k1_scorer(const float* __restrict__ h_t,
                          const float* __restrict__ W,
                          const float* __restrict__ bmap) {
    int tid = threadIdx.x;               // 256
    int bq = tid >> 7, f = tid & 127;
    int b0 = blockIdx.x * 2;
    __shared__ float Ws[64 * 128];
    __shared__ float hs[2 * RNN];
    __shared__ float red2[8];
    for (int i = tid; i < 2 * RNN; i += 256)
        hs[i] = h_t[b0 * RNN + i];
    float acc = bmap[f];
    float4* Ws4 = reinterpret_cast<float4*>(Ws);
    for (int c = 0; c < RNN / 64; ++c) {
        __syncthreads();
        const float4* W4 = reinterpret_cast<const float4*>(W + c * 64 * 128);
#pragma unroll
        for (int i = 0; i < 8; ++i) Ws4[tid + i * 256] = W4[tid + i * 256];
        __syncthreads();
        const float* hb = hs + bq * RNN + c * 64;
#pragma unroll
        for (int r = 0; r < 64; ++r) acc = fmaf(hb[r], Ws[r * 128 + f], acc);
    }
    float s = tanhf(acc);
    float q = s * s;
#pragma unroll
    for (int o = 16; o > 0; o >>= 1) q += __shfl_xor_sync(0xffffffffu, q, o);
    int warp = tid >> 5, lane = tid & 31;
    if (lane == 0) red2[warp] = q;
    __syncthreads();
    float nrm = red2[bq * 4] + red2[bq * 4 + 1] + red2[bq * 4 + 2] + red2[bq * 4 + 3];
    g_scorer[(b0 + bq) * FF + f] = s * rsqrtf(nrm);
}

// --------------------------------------------------------------------------
// K2: scores[b,g] = node_embs[b,g,:] . scorer[b,:] + mask[b,g]
//     warp per row, 8 rows in flight, __ldcs evict-first streaming
//     (measured: __ldcs is worth ~10 us vs default policy on this stream)
// --------------------------------------------------------------------------
__global__ void k2_scores(const float* __restrict__ ne,
                          const float* __restrict__ mask) {
    int b = blockIdx.x;
    int gbase = blockIdx.y * 64;
    __shared__ float4 sc[FF / 4];
    int tid = threadIdx.x;                   // 256
    if (tid < FF / 4)
        sc[tid] = reinterpret_cast<const float4*>(g_scorer + b * FF)[tid];
    __syncthreads();
    int warp = tid >> 5, lane = tid & 31;
    float4 s = sc[lane];
    const float4* base = reinterpret_cast<const float4*>(ne) + (size_t)b * GG * (FF / 4);
    int g0 = gbase + warp * 8;
    float d[8];
#pragma unroll
    for (int j = 0; j < 8; ++j) {
        float4 v = __ldcs(base + (size_t)(g0 + j) * (FF / 4) + lane);
        d[j] = v.x * s.x + v.y * s.y + v.z * s.z + v.w * s.w;
    }
#pragma unroll
    for (int o = 16; o > 0; o >>= 1) {
#pragma unroll
        for (int j = 0; j < 8; ++j) d[j] += __shfl_xor_sync(0xffffffffu, d[j], o);
    }
    if (lane == 0) {
        const float4* mb = reinterpret_cast<const float4*>(mask + b * GG + g0);
        float4* ob = reinterpret_cast<float4*>(g_scores + b * GG + g0);
        float4 m0 = mb[0], m1 = mb[1];
        ob[0] = make_float4(d[0] + m0.x, d[1] + m0.y, d[2] + m0.z, d[3] + m0.w);
        ob[1] = make_float4(d[4] + m1.x, d[5] + m1.y, d[6] + m1.z, d[7] + m1.w);
    }
}

// --------------------------------------------------------------------------
// K3: 32-bit radix-select top-128 + rank-by-count emit + logsumexp
// --------------------------------------------------------------------------
__device__ __forceinline__ unsigned f2u(float f) {
    unsigned u = __float_as_uint(f);
    return (u & 0x80000000u) ? ~u : (u | 0x80000000u);
}
__device__ __forceinline__ float u2f(unsigned u) {
    unsigned b = (u & 0x80000000u) ? (u & 0x7FFFFFFFu) : ~u;
    return __uint_as_float(b);
}

__global__ void k3_topk(float* __restrict__ policy_out) {
    const unsigned FULL = 0xffffffffu;
    int b = blockIdx.x, tid = threadIdx.x;   // 512 threads, 16 warps
    int lane = tid & 31, warp = tid >> 5;
    __shared__ float rbuf[16];
    __shared__ unsigned hist[256];
    __shared__ unsigned long long top[256];
    __shared__ unsigned sel_d, sel_sub, cnt_;
    __shared__ float s_smax;

    float v[4];
    unsigned u[4];
#pragma unroll
    for (int j = 0; j < 4; ++j) {
        v[j] = g_scores[b * GG + tid + j * 512];
        u[j] = f2u(v[j]);
    }

    unsigned prefix = 0, kneed = KK;
    for (int shift = 24; shift >= 0; shift -= 8) {
        unsigned maskhi = (shift == 24) ? 0u : (0xFFFFFFFFu << (shift + 8));
        __syncthreads();
        if (tid < 256) hist[tid] = 0;
        __syncthreads();
#pragma unroll
        for (int j = 0; j < 4; ++j)
            if ((u[j] & maskhi) == prefix)
                atomicAdd(&hist[(u[j] >> shift) & 0xFFu], 1u);
        __syncthreads();
        if (tid < 32) {
            unsigned hv[8], t = 0;
#pragma unroll
            for (int q = 0; q < 8; ++q) { hv[q] = hist[tid * 8 + q]; t += hv[q]; }
            unsigned x = t;
#pragma unroll
            for (int o = 1; o < 32; o <<= 1) {
                unsigned y = __shfl_down_sync(FULL, x, o);
                if (tid + o < 32) x += y;
            }
            unsigned run = x - t;
#pragma unroll
            for (int q = 7; q >= 0; --q) { run += hv[q]; hist[tid * 8 + q] = run; }
        }
        __syncthreads();
        if (tid < 256) {
            unsigned h = hist[tid];
            unsigned hn = (tid == 255) ? 0u : hist[tid + 1];
            if (h >= kneed && hn < kneed) { sel_d = (unsigned)tid; sel_sub = hn; }
        }
        __syncthreads();
        prefix |= sel_d << shift;
        kneed -= sel_sub;
    }

    if (tid == 0) cnt_ = 0;
    __syncthreads();
#pragma unroll
    for (int j = 0; j < 4; ++j) {
        if (u[j] >= prefix) {
            unsigned p = atomicAdd(&cnt_, 1u);
            if (p < 256)
                top[p] = ((unsigned long long)u[j] << 32) |
                         (unsigned)(~(unsigned)(tid + j * 512));
        }
    }
    __syncthreads();
    unsigned n = cnt_ < 256u ? cnt_ : 256u;

    float contrib = 0.f;
    if (tid < (int)n) {
        unsigned long long key = top[tid];
        unsigned r = 0;
        for (unsigned jj = 0; jj < n; ++jj) r += (top[jj] > key);
        if (r < KK) {
            float val = u2f((unsigned)(key >> 32));
            g_tvals[b * KK + r] = tanhf(val);
            g_tidx [b * KK + r] = (int)(~(unsigned)key);
            contrib = val;
            if (r == 0) s_smax = val;
        }
    }
#pragma unroll
    for (int o = 16; o > 0; o >>= 1) contrib += __shfl_xor_sync(FULL, contrib, o);
    if (lane == 0) rbuf[warp] = contrib;
    __syncthreads();
    float sumtop = 0.f;
    if (tid == 0) {
#pragma unroll
        for (int w = 0; w < 16; ++w) sumtop += rbuf[w];
    }
    float smax = s_smax;
    __syncthreads();

    float sum = expf(v[0] - smax) + expf(v[1] - smax) +
                expf(v[2] - smax) + expf(v[3] - smax);
#pragma unroll
    for (int o = 16; o > 0; o >>= 1) sum += __shfl_xor_sync(FULL, sum, o);
    if (lane == 0) rbuf[warp] = sum;
    __syncthreads();
    if (tid == 0) {
        float x = 0.f;
#pragma unroll
        for (int w = 0; w < 16; ++w) x += rbuf[w];
        policy_out[b] = sumtop * (1.0f / KK) - (smax + logf(x));
    }
}

// --------------------------------------------------------------------------
// K4: out[b,f,k] = node_embs[b, idx[b,k], f] * tanh(val[b,k])
//     4 blocks/batch, 32-row tiles, 4 front-batched LDG.128/thread
// --------------------------------------------------------------------------
__global__ void k4_gather(const float* __restrict__ ne, float* __restrict__ out) {
    int b = blockIdx.x, kq = blockIdx.y;     // quarter index 0..3
    int tid = threadIdx.x;                   // 256 threads
    __shared__ float tile[32 * 129];
    __shared__ float tv[32];
    __shared__ int   ti[32];
    if (tid < 32) {
        tv[tid] = g_tvals[b * KK + kq * 32 + tid];
        ti[tid] = g_tidx [b * KK + kq * 32 + tid];
    }
    __syncthreads();
    const float4* base = reinterpret_cast<const float4*>(ne) + (size_t)b * GG * (FF / 4);
    float* ob = out + (size_t)b * FF * KK + kq * 32;
#pragma unroll
    for (int it = 0; it < 4; ++it) {
        int i = tid + it * 256;              // 0..1023
        int k = i >> 5, c = i & 31;
        float4 v = base[(size_t)ti[k] * (FF / 4) + c];
        float s = tv[k];
        float* t = tile + k * 129 + c * 4;
        t[0] = v.x * s; t[1] = v.y * s; t[2] = v.z * s; t[3] = v.w * s;
    }
    __syncthreads();
#pragma unroll
    for (int it = 0; it < 4; ++it) {
        int i = tid + it * 256;              // 0..1023
        int f = i >> 3, q = i & 7;
        int k = q * 4;
        float4 w;
        w.x = tile[(k + 0) * 129 + f];
        w.y = tile[(k + 1) * 129 + f];
        w.z = tile[(k + 2) * 129 + f];
        w.w = tile[(k + 3) * 129 + f];
        *reinterpret_cast<float4*>(ob + (size_t)f * KK + k) = w;
    }
}

// --------------------------------------------------------------------------
extern "C" void kernel_launch(void* const* d_in, const int* in_sizes, int n_in,
                              void* d_out, int out_size) {
    const float* node_embs = (const float*)d_in[0];
    const float* mask      = (const float*)d_in[1];
    const float* h_t       = (const float*)d_in[2];
    const float* W_map     = (const float*)d_in[3];
    const float* b_map     = (const float*)d_in[4];
    float* out    = (float*)d_out;
    float* policy = out + (size_t)BB * FF * KK;   // outputs: [B,F,K] then [B]

    k1_scorer<<<BB / 2, 256>>>(h_t, W_map, b_map);
    k2_scores<<<dim3(BB, GG / 64), 256>>>(node_embs, mask);
    k3_topk<<<BB, 512>>>(policy);
    k4_gather<<<dim3(BB, 4), 256>>>(node_embs, out);
}

// round 15
// speedup vs baseline: 1.1509x; 1.0149x over previous
#include <cuda_runtime.h>
#include <math.h>

#define BB  256
#define GG  2048
#define FF  128
#define RNN 512
#define KK  128

// Scratch (no allocation allowed) ------------------------------------------
__device__ float g_scorer[BB * FF];
__device__ float g_scores[BB * GG];
__device__ float g_tvals [BB * KK];
__device__ int   g_tidx  [BB * KK];

// --------------------------------------------------------------------------
// K1: scorer[b,f] = tanh(h_t[b,:] @ W[:,f] + bias[f]) / ||tanh||
//     (round-6: 128 blocks x 256 threads, 2 batches/block) — UNCHANGED
// --------------------------------------------------------------------------
__global__ void k1_scorer(const float* __restrict__ h_t,
                          const float* __restrict__ W,
                          const float* __restrict__ bmap) {
    int tid = threadIdx.x;               // 256
    int bq = tid >> 7, f = tid & 127;
    int b0 = blockIdx.x * 2;
    __shared__ float Ws[64 * 128];
    __shared__ float hs[2 * RNN];
    __shared__ float red2[8];
    for (int i = tid; i < 2 * RNN; i += 256)
        hs[i] = h_t[b0 * RNN + i];
    float acc = bmap[f];
    float4* Ws4 = reinterpret_cast<float4*>(Ws);
    for (int c = 0; c < RNN / 64; ++c) {
        __syncthreads();
        const float4* W4 = reinterpret_cast<const float4*>(W + c * 64 * 128);
#pragma unroll
        for (int i = 0; i < 8; ++i) Ws4[tid + i * 256] = W4[tid + i * 256];
        __syncthreads();
        const float* hb = hs + bq * RNN + c * 64;
#pragma unroll
        for (int r = 0; r < 64; ++r) acc = fmaf(hb[r], Ws[r * 128 + f], acc);
    }
    float s = tanhf(acc);
    float q = s * s;
#pragma unroll
    for (int o = 16; o > 0; o >>= 1) q += __shfl_xor_sync(0xffffffffu, q, o);
    int warp = tid >> 5, lane = tid & 31;
    if (lane == 0) red2[warp] = q;
    __syncthreads();
    float nrm = red2[bq * 4] + red2[bq * 4 + 1] + red2[bq * 4 + 2] + red2[bq * 4 + 3];
    g_scorer[(b0 + bq) * FF + f] = s * rsqrtf(nrm);
}

// --------------------------------------------------------------------------
// K2: scores[b,g] = node_embs[b,g,:] . scorer[b,:] + mask[b,g]
//     (round-6: warp per row, 8 rows in flight, __ldcs) — UNCHANGED
// --------------------------------------------------------------------------
__global__ void k2_scores(const float* __restrict__ ne,
                          const float* __restrict__ mask) {
    int b = blockIdx.x;
    int gbase = blockIdx.y * 64;
    __shared__ float4 sc[FF / 4];
    int tid = threadIdx.x;                   // 256
    if (tid < FF / 4)
        sc[tid] = reinterpret_cast<const float4*>(g_scorer + b * FF)[tid];
    __syncthreads();
    int warp = tid >> 5, lane = tid & 31;
    float4 s = sc[lane];
    const float4* base = reinterpret_cast<const float4*>(ne) + (size_t)b * GG * (FF / 4);
    int g0 = gbase + warp * 8;
    float d[8];
#pragma unroll
    for (int j = 0; j < 8; ++j) {
        float4 v = __ldcs(base + (size_t)(g0 + j) * (FF / 4) + lane);
        d[j] = v.x * s.x + v.y * s.y + v.z * s.z + v.w * s.w;
    }
#pragma unroll
    for (int o = 16; o > 0; o >>= 1) {
#pragma unroll
        for (int j = 0; j < 8; ++j) d[j] += __shfl_xor_sync(0xffffffffu, d[j], o);
    }
    if (lane == 0) {
        const float4* mb = reinterpret_cast<const float4*>(mask + b * GG + g0);
        float4* ob = reinterpret_cast<float4*>(g_scores + b * GG + g0);
        float4 m0 = mb[0], m1 = mb[1];
        ob[0] = make_float4(d[0] + m0.x, d[1] + m0.y, d[2] + m0.z, d[3] + m0.w);
        ob[1] = make_float4(d[4] + m1.x, d[5] + m1.y, d[6] + m1.z, d[7] + m1.w);
    }
}

// --------------------------------------------------------------------------
// K3 (PDL entry sync): 32-bit radix-select top-128 + rank emit + logsumexp
// --------------------------------------------------------------------------
__device__ __forceinline__ unsigned f2u(float f) {
    unsigned u = __float_as_uint(f);
    return (u & 0x80000000u) ? ~u : (u | 0x80000000u);
}
__device__ __forceinline__ float u2f(unsigned u) {
    unsigned b = (u & 0x80000000u) ? (u & 0x7FFFFFFFu) : ~u;
    return __uint_as_float(b);
}

__global__ void k3_topk(float* __restrict__ policy_out) {
    const unsigned FULL = 0xffffffffu;
    int b = blockIdx.x, tid = threadIdx.x;   // 512 threads, 16 warps
    int lane = tid & 31, warp = tid >> 5;
    __shared__ float rbuf[16];
    __shared__ unsigned hist[256];
    __shared__ unsigned long long top[256];
    __shared__ unsigned sel_d, sel_sub, cnt_;
    __shared__ float s_smax;

    cudaGridDependencySynchronize();         // wait for k2's g_scores

    float v[4];
    unsigned u[4];
#pragma unroll
    for (int j = 0; j < 4; ++j) {
        v[j] = g_scores[b * GG + tid + j * 512];
        u[j] = f2u(v[j]);
    }

    unsigned prefix = 0, kneed = KK;
    for (int shift = 24; shift >= 0; shift -= 8) {
        unsigned maskhi = (shift == 24) ? 0u : (0xFFFFFFFFu << (shift + 8));
        __syncthreads();
        if (tid < 256) hist[tid] = 0;
        __syncthreads();
#pragma unroll
        for (int j = 0; j < 4; ++j)
            if ((u[j] & maskhi) == prefix)
                atomicAdd(&hist[(u[j] >> shift) & 0xFFu], 1u);
        __syncthreads();
        if (tid < 32) {
            unsigned hv[8], t = 0;
#pragma unroll
            for (int q = 0; q < 8; ++q) { hv[q] = hist[tid * 8 + q]; t += hv[q]; }
            unsigned x = t;
#pragma unroll
            for (int o = 1; o < 32; o <<= 1) {
                unsigned y = __shfl_down_sync(FULL, x, o);
                if (tid + o < 32) x += y;
            }
            unsigned run = x - t;
#pragma unroll
            for (int q = 7; q >= 0; --q) { run += hv[q]; hist[tid * 8 + q] = run; }
        }
        __syncthreads();
        if (tid < 256) {
            unsigned h = hist[tid];
            unsigned hn = (tid == 255) ? 0u : hist[tid + 1];
            if (h >= kneed && hn < kneed) { sel_d = (unsigned)tid; sel_sub = hn; }
        }
        __syncthreads();
        prefix |= sel_d << shift;
        kneed -= sel_sub;
    }

    if (tid == 0) cnt_ = 0;
    __syncthreads();
#pragma unroll
    for (int j = 0; j < 4; ++j) {
        if (u[j] >= prefix) {
            unsigned p = atomicAdd(&cnt_, 1u);
            if (p < 256)
                top[p] = ((unsigned long long)u[j] << 32) |
                         (unsigned)(~(unsigned)(tid + j * 512));
        }
    }
    __syncthreads();
    unsigned n = cnt_ < 256u ? cnt_ : 256u;

    float contrib = 0.f;
    if (tid < (int)n) {
        unsigned long long key = top[tid];
        unsigned r = 0;
        for (unsigned jj = 0; jj < n; ++jj) r += (top[jj] > key);
        if (r < KK) {
            float val = u2f((unsigned)(key >> 32));
            g_tvals[b * KK + r] = tanhf(val);
            g_tidx [b * KK + r] = (int)(~(unsigned)key);
            contrib = val;
            if (r == 0) s_smax = val;
        }
    }
#pragma unroll
    for (int o = 16; o > 0; o >>= 1) contrib += __shfl_xor_sync(FULL, contrib, o);
    if (lane == 0) rbuf[warp] = contrib;
    __syncthreads();
    float sumtop = 0.f;
    if (tid == 0) {
#pragma unroll
        for (int w = 0; w < 16; ++w) sumtop += rbuf[w];
    }
    float smax = s_smax;
    __syncthreads();

    float sum = expf(v[0] - smax) + expf(v[1] - smax) +
                expf(v[2] - smax) + expf(v[3] - smax);
#pragma unroll
    for (int o = 16; o > 0; o >>= 1) sum += __shfl_xor_sync(FULL, sum, o);
    if (lane == 0) rbuf[warp] = sum;
    __syncthreads();
    if (tid == 0) {
        float x = 0.f;
#pragma unroll
        for (int w = 0; w < 16; ++w) x += rbuf[w];
        policy_out[b] = sumtop * (1.0f / KK) - (smax + logf(x));
    }
}

// --------------------------------------------------------------------------
// K4 (PDL entry sync): out[b,f,k] = node_embs[b, idx[b,k], f] * tanh(val)
//     (round-6: 4 blocks/batch, 32-row tiles, 4 LDG.128/thread)
// --------------------------------------------------------------------------
__global__ void k4_gather(const float* __restrict__ ne, float* __restrict__ out) {
    int b = blockIdx.x, kq = blockIdx.y;     // quarter index 0..3
    int tid = threadIdx.x;                   // 256 threads
    __shared__ float tile[32 * 129];
    __shared__ float tv[32];
    __shared__ int   ti[32];

    cudaGridDependencySynchronize();         // wait for k3's tvals/tidx

    if (tid < 32) {
        tv[tid] = g_tvals[b * KK + kq * 32 + tid];
        ti[tid] = g_tidx [b * KK + kq * 32 + tid];
    }
    __syncthreads();
    const float4* base = reinterpret_cast<const float4*>(ne) + (size_t)b * GG * (FF / 4);
    float* ob = out + (size_t)b * FF * KK + kq * 32;
#pragma unroll
    for (int it = 0; it < 4; ++it) {
        int i = tid + it * 256;              // 0..1023
        int k = i >> 5, c = i & 31;
        float4 v = base[(size_t)ti[k] * (FF / 4) + c];
        float s = tv[k];
        float* t = tile + k * 129 + c * 4;
        t[0] = v.x * s; t[1] = v.y * s; t[2] = v.z * s; t[3] = v.w * s;
    }
    __syncthreads();
#pragma unroll
    for (int it = 0; it < 4; ++it) {
        int i = tid + it * 256;              // 0..1023
        int f = i >> 3, q = i & 7;
        int k = q * 4;
        float4 w;
        w.x = tile[(k + 0) * 129 + f];
        w.y = tile[(k + 1) * 129 + f];
        w.z = tile[(k + 2) * 129 + f];
        w.w = tile[(k + 3) * 129 + f];
        *reinterpret_cast<float4*>(ob + (size_t)f * KK + k) = w;
    }
}

// --------------------------------------------------------------------------
static inline void launch_pdl(void* fn, dim3 grid, dim3 block, void** args) {
    cudaLaunchConfig_t cfg = {};
    cfg.gridDim = grid;
    cfg.blockDim = block;
    cudaLaunchAttribute attr[1];
    attr[0].id = cudaLaunchAttributeProgrammaticStreamSerialization;
    attr[0].val.programmaticStreamSerializationAllowed = 1;
    cfg.attrs = attr;
    cfg.numAttrs = 1;
    cudaLaunchKernelExC(&cfg, fn, args);
}

extern "C" void kernel_launch(void* const* d_in, const int* in_sizes, int n_in,
                              void* d_out, int out_size) {
    const float* node_embs = (const float*)d_in[0];
    const float* mask      = (const float*)d_in[1];
    const float* h_t       = (const float*)d_in[2];
    const float* W_map     = (const float*)d_in[3];
    const float* b_map     = (const float*)d_in[4];
    float* out    = (float*)d_out;
    float* policy = out + (size_t)BB * FF * KK;   // outputs: [B,F,K] then [B]

    k1_scorer<<<BB / 2, 256>>>(h_t, W_map, b_map);
    k2_scores<<<dim3(BB, GG / 64), 256>>>(node_embs, mask);
    {   // k3: PDL — resident during k2 drain, syncs on g_scores
        void* args[] = { (void*)&policy };
        launch_pdl((void*)k3_topk, dim3(BB), dim3(512), args);
    }
    {   // k4: PDL — overlaps k3 tail, syncs on tvals/tidx
        void* args[] = { (void*)&node_embs, (void*)&out };
        launch_pdl((void*)k4_gather, dim3(BB, 4), dim3(256), args);
    }
}

// round 16
// speedup vs baseline: 1.1607x; 1.0085x over previous
#include <cuda_runtime.h>
#include <math.h>

#define BB  256
#define GG  2048
#define FF  128
#define RNN 512
#define KK  128

// Scratch (no allocation allowed) ------------------------------------------
__device__ float g_scorer[BB * FF];
__device__ float g_scores[BB * GG];
__device__ float g_tvals [BB * KK];
__device__ int   g_tidx  [BB * KK];

// --------------------------------------------------------------------------
// K1: scorer[b,f] = tanh(h_t[b,:] @ W[:,f] + bias[f]) / ||tanh||
//     (round-6: 128 blocks x 256 threads, 2 batches/block) — UNCHANGED
// --------------------------------------------------------------------------
__global__ void k1_scorer(const float* __restrict__ h_t,
                          const float* __restrict__ W,
                          const float* __restrict__ bmap) {
    int tid = threadIdx.x;               // 256
    int bq = tid >> 7, f = tid & 127;
    int b0 = blockIdx.x * 2;
    __shared__ float Ws[64 * 128];
    __shared__ float hs[2 * RNN];
    __shared__ float red2[8];
    for (int i = tid; i < 2 * RNN; i += 256)
        hs[i] = h_t[b0 * RNN + i];
    float acc = bmap[f];
    float4* Ws4 = reinterpret_cast<float4*>(Ws);
    for (int c = 0; c < RNN / 64; ++c) {
        __syncthreads();
        const float4* W4 = reinterpret_cast<const float4*>(W + c * 64 * 128);
#pragma unroll
        for (int i = 0; i < 8; ++i) Ws4[tid + i * 256] = W4[tid + i * 256];
        __syncthreads();
        const float* hb = hs + bq * RNN + c * 64;
#pragma unroll
        for (int r = 0; r < 64; ++r) acc = fmaf(hb[r], Ws[r * 128 + f], acc);
    }
    float s = tanhf(acc);
    float q = s * s;
#pragma unroll
    for (int o = 16; o > 0; o >>= 1) q += __shfl_xor_sync(0xffffffffu, q, o);
    int warp = tid >> 5, lane = tid & 31;
    if (lane == 0) red2[warp] = q;
    __syncthreads();
    float nrm = red2[bq * 4] + red2[bq * 4 + 1] + red2[bq * 4 + 2] + red2[bq * 4 + 3];
    g_scorer[(b0 + bq) * FF + f] = s * rsqrtf(nrm);
}

// --------------------------------------------------------------------------
// K2 (PDL entry sync): scores[b,g] = node_embs[b,g,:].scorer[b,:] + mask
//     body identical to round-6 (__ldcs, 8 rows/warp); sync at top only
// --------------------------------------------------------------------------
__global__ void k2_scores(const float* __restrict__ ne,
                          const float* __restrict__ mask) {
    int b = blockIdx.x;
    int gbase = blockIdx.y * 64;
    __shared__ float4 sc[FF / 4];
    int tid = threadIdx.x;                   // 256

    cudaGridDependencySynchronize();         // wait for k1's g_scorer

    if (tid < FF / 4)
        sc[tid] = reinterpret_cast<const float4*>(g_scorer + b * FF)[tid];
    __syncthreads();
    int warp = tid >> 5, lane = tid & 31;
    float4 s = sc[lane];
    const float4* base = reinterpret_cast<const float4*>(ne) + (size_t)b * GG * (FF / 4);
    int g0 = gbase + warp * 8;
    float d[8];
#pragma unroll
    for (int j = 0; j < 8; ++j) {
        float4 v = __ldcs(base + (size_t)(g0 + j) * (FF / 4) + lane);
        d[j] = v.x * s.x + v.y * s.y + v.z * s.z + v.w * s.w;
    }
#pragma unroll
    for (int o = 16; o > 0; o >>= 1) {
#pragma unroll
        for (int j = 0; j < 8; ++j) d[j] += __shfl_xor_sync(0xffffffffu, d[j], o);
    }
    if (lane == 0) {
        const float4* mb = reinterpret_cast<const float4*>(mask + b * GG + g0);
        float4* ob = reinterpret_cast<float4*>(g_scores + b * GG + g0);
        float4 m0 = mb[0], m1 = mb[1];
        ob[0] = make_float4(d[0] + m0.x, d[1] + m0.y, d[2] + m0.z, d[3] + m0.w);
        ob[1] = make_float4(d[4] + m1.x, d[5] + m1.y, d[6] + m1.z, d[7] + m1.w);
    }
}

// --------------------------------------------------------------------------
// K3 (PDL entry sync): 32-bit radix-select top-128 + rank emit + logsumexp
// --------------------------------------------------------------------------
__device__ __forceinline__ unsigned f2u(float f) {
    unsigned u = __float_as_uint(f);
    return (u & 0x80000000u) ? ~u : (u | 0x80000000u);
}
__device__ __forceinline__ float u2f(unsigned u) {
    unsigned b = (u & 0x80000000u) ? (u & 0x7FFFFFFFu) : ~u;
    return __uint_as_float(b);
}

__global__ void k3_topk(float* __restrict__ policy_out) {
    const unsigned FULL = 0xffffffffu;
    int b = blockIdx.x, tid = threadIdx.x;   // 512 threads, 16 warps
    int lane = tid & 31, warp = tid >> 5;
    __shared__ float rbuf[16];
    __shared__ unsigned hist[256];
    __shared__ unsigned long long top[256];
    __shared__ unsigned sel_d, sel_sub, cnt_;
    __shared__ float s_smax;

    cudaGridDependencySynchronize();         // wait for k2's g_scores

    float v[4];
    unsigned u[4];
#pragma unroll
    for (int j = 0; j < 4; ++j) {
        v[j] = g_scores[b * GG + tid + j * 512];
        u[j] = f2u(v[j]);
    }

    unsigned prefix = 0, kneed = KK;
    for (int shift = 24; shift >= 0; shift -= 8) {
        unsigned maskhi = (shift == 24) ? 0u : (0xFFFFFFFFu << (shift + 8));
        __syncthreads();
        if (tid < 256) hist[tid] = 0;
        __syncthreads();
#pragma unroll
        for (int j = 0; j < 4; ++j)
            if ((u[j] & maskhi) == prefix)
                atomicAdd(&hist[(u[j] >> shift) & 0xFFu], 1u);
        __syncthreads();
        if (tid < 32) {
            unsigned hv[8], t = 0;
#pragma unroll
            for (int q = 0; q < 8; ++q) { hv[q] = hist[tid * 8 + q]; t += hv[q]; }
            unsigned x = t;
#pragma unroll
            for (int o = 1; o < 32; o <<= 1) {
                unsigned y = __shfl_down_sync(FULL, x, o);
                if (tid + o < 32) x += y;
            }
            unsigned run = x - t;
#pragma unroll
            for (int q = 7; q >= 0; --q) { run += hv[q]; hist[tid * 8 + q] = run; }
        }
        __syncthreads();
        if (tid < 256) {
            unsigned h = hist[tid];
            unsigned hn = (tid == 255) ? 0u : hist[tid + 1];
            if (h >= kneed && hn < kneed) { sel_d = (unsigned)tid; sel_sub = hn; }
        }
        __syncthreads();
        prefix |= sel_d << shift;
        kneed -= sel_sub;
    }

    if (tid == 0) cnt_ = 0;
    __syncthreads();
#pragma unroll
    for (int j = 0; j < 4; ++j) {
        if (u[j] >= prefix) {
            unsigned p = atomicAdd(&cnt_, 1u);
            if (p < 256)
                top[p] = ((unsigned long long)u[j] << 32) |
                         (unsigned)(~(unsigned)(tid + j * 512));
        }
    }
    __syncthreads();
    unsigned n = cnt_ < 256u ? cnt_ : 256u;

    float contrib = 0.f;
    if (tid < (int)n) {
        unsigned long long key = top[tid];
        unsigned r = 0;
        for (unsigned jj = 0; jj < n; ++jj) r += (top[jj] > key);
        if (r < KK) {
            float val = u2f((unsigned)(key >> 32));
            g_tvals[b * KK + r] = tanhf(val);
            g_tidx [b * KK + r] = (int)(~(unsigned)key);
            contrib = val;
            if (r == 0) s_smax = val;
        }
    }
#pragma unroll
    for (int o = 16; o > 0; o >>= 1) contrib += __shfl_xor_sync(FULL, contrib, o);
    if (lane == 0) rbuf[warp] = contrib;
    __syncthreads();
    float sumtop = 0.f;
    if (tid == 0) {
#pragma unroll
        for (int w = 0; w < 16; ++w) sumtop += rbuf[w];
    }
    float smax = s_smax;
    __syncthreads();

    float sum = expf(v[0] - smax) + expf(v[1] - smax) +
                expf(v[2] - smax) + expf(v[3] - smax);
#pragma unroll
    for (int o = 16; o > 0; o >>= 1) sum += __shfl_xor_sync(FULL, sum, o);
    if (lane == 0) rbuf[warp] = sum;
    __syncthreads();
    if (tid == 0) {
        float x = 0.f;
#pragma unroll
        for (int w = 0; w < 16; ++w) x += rbuf[w];
        policy_out[b] = sumtop * (1.0f / KK) - (smax + logf(x));
    }
}

// --------------------------------------------------------------------------
// K4 (PDL entry sync): out[b,f,k] = node_embs[b, idx[b,k], f] * tanh(val)
//     (round-6: 4 blocks/batch, 32-row tiles, 4 LDG.128/thread)
// --------------------------------------------------------------------------
__global__ void k4_gather(const float* __restrict__ ne, float* __restrict__ out) {
    int b = blockIdx.x, kq = blockIdx.y;     // quarter index 0..3
    int tid = threadIdx.x;                   // 256 threads
    __shared__ float tile[32 * 129];
    __shared__ float tv[32];
    __shared__ int   ti[32];

    cudaGridDependencySynchronize();         // wait for k3's tvals/tidx

    if (tid < 32) {
        tv[tid] = g_tvals[b * KK + kq * 32 + tid];
        ti[tid] = g_tidx [b * KK + kq * 32 + tid];
    }
    __syncthreads();
    const float4* base = reinterpret_cast<const float4*>(ne) + (size_t)b * GG * (FF / 4);
    float* ob = out + (size_t)b * FF * KK + kq * 32;
#pragma unroll
    for (int it = 0; it < 4; ++it) {
        int i = tid + it * 256;              // 0..1023
        int k = i >> 5, c = i & 31;
        float4 v = base[(size_t)ti[k] * (FF / 4) + c];
        float s = tv[k];
        float* t = tile + k * 129 + c * 4;
        t[0] = v.x * s; t[1] = v.y * s; t[2] = v.z * s; t[3] = v.w * s;
    }
    __syncthreads();
#pragma unroll
    for (int it = 0; it < 4; ++it) {
        int i = tid + it * 256;              // 0..1023
        int f = i >> 3, q = i & 7;
        int k = q * 4;
        float4 w;
        w.x = tile[(k + 0) * 129 + f];
        w.y = tile[(k + 1) * 129 + f];
        w.z = tile[(k + 2) * 129 + f];
        w.w = tile[(k + 3) * 129 + f];
        *reinterpret_cast<float4*>(ob + (size_t)f * KK + k) = w;
    }
}

// --------------------------------------------------------------------------
static inline void launch_pdl(void* fn, dim3 grid, dim3 block, void** args) {
    cudaLaunchConfig_t cfg = {};
    cfg.gridDim = grid;
    cfg.blockDim = block;
    cudaLaunchAttribute attr[1];
    attr[0].id = cudaLaunchAttributeProgrammaticStreamSerialization;
    attr[0].val.programmaticStreamSerializationAllowed = 1;
    cfg.attrs = attr;
    cfg.numAttrs = 1;
    cudaLaunchKernelExC(&cfg, fn, args);
}

extern "C" void kernel_launch(void* const* d_in, const int* in_sizes, int n_in,
                              void* d_out, int out_size) {
    const float* node_embs = (const float*)d_in[0];
    const float* mask      = (const float*)d_in[1];
    const float* h_t       = (const float*)d_in[2];
    const float* W_map     = (const float*)d_in[3];
    const float* b_map     = (const float*)d_in[4];
    float* out    = (float*)d_out;
    float* policy = out + (size_t)BB * FF * KK;   // outputs: [B,F,K] then [B]

    k1_scorer<<<BB / 2, 256>>>(h_t, W_map, b_map);
    {   // k2: PDL — resident during k1 tail, syncs on g_scorer
        void* args[] = { (void*)&node_embs, (void*)&mask };
        launch_pdl((void*)k2_scores, dim3(BB, GG / 64), dim3(256), args);
    }
    {   // k3: PDL — resident during k2 drain, syncs on g_scores
        void* args[] = { (void*)&policy };
        launch_pdl((void*)k3_topk, dim3(BB), dim3(512), args);
    }
    {   // k4: PDL — overlaps k3 tail, syncs on tvals/tidx
        void* args[] = { (void*)&node_embs, (void*)&out };
        launch_pdl((void*)k4_gather, dim3(BB, 4), dim3(256), args);
    }
}